// round 14
// baseline (speedup 1.0000x reference)
#include <cuda_runtime.h>
#include <cuda_fp16.h>
#include <math.h>
#include <stdint.h>

#define BB 16
#define NN 512
#define DD 768
#define HH 8
#define FF 96
#define GM (BB*NN)      /* 8192 rows */
#define GN (2*DD)       /* 1536 cols: [0,768)=h proj, [768,1536)=gate */
#define GK DD           /* 768 */

// ---------------- scratch (device globals; no allocs allowed) ----------------
__device__ __half g_hh[BB*HH*NN*FF];        // fp16 hi of h, [bh][n][f]
__device__ __half g_hl[BB*HH*NN*FF];        // fp16 lo of h
__device__ float g_es1[BB*HH*NN];           // exp(s)
__device__ float g_es2[BB*HH*NN];           // exp(0.2 s)
__device__ float g_ed1[BB*HH*NN];           // exp(d)
__device__ float g_ed2[BB*HH*NN];           // exp(0.2 d)
__device__ float g_gate[BB*NN*DD];          // sigmoid, SEMANTIC-LINEAR [B,N,D]
__device__ float g_x1[BB*NN*DD];            // layer-0 output (linear [B,N,D])
__device__ __half g_Ah[GM*GK];              // fp16 activations (linear [B,N,D])
__device__ __half g_Bh[2][GN*GK];           // packed weights fp16 [N=1536][K=768]

// ============================ PTX helpers (base sm_103 only) =================
__device__ __forceinline__ uint32_t smem_u32(const void* p) {
    uint32_t a;
    asm("{ .reg .u64 t; cvta.to.shared.u64 t, %1; cvt.u32.u64 %0, t; }"
        : "=r"(a) : "l"(p));
    return a;
}

__device__ __forceinline__ void cpasync16(uint32_t saddr, const void* g) {
    asm volatile("cp.async.cg.shared.global [%0], [%1], 16;"
                 :: "r"(saddr), "l"(g) : "memory");
}
#define CP_COMMIT() asm volatile("cp.async.commit_group;" ::: "memory")
template<int N> __device__ __forceinline__ void cp_wait() {
    asm volatile("cp.async.wait_group %0;" :: "n"(N) : "memory");
}

__device__ __forceinline__ void ldsm4(uint32_t* r, uint32_t addr) {
    asm volatile("ldmatrix.sync.aligned.m8n8.x4.shared.b16 {%0,%1,%2,%3}, [%4];"
                 : "=r"(r[0]), "=r"(r[1]), "=r"(r[2]), "=r"(r[3]) : "r"(addr));
}
__device__ __forceinline__ void ldsm4t(uint32_t* r, uint32_t addr) {
    asm volatile("ldmatrix.sync.aligned.m8n8.x4.trans.shared.b16 {%0,%1,%2,%3}, [%4];"
                 : "=r"(r[0]), "=r"(r[1]), "=r"(r[2]), "=r"(r[3]) : "r"(addr));
}

__device__ __forceinline__ void mma_f16(float* c, const uint32_t* a,
                                        uint32_t b0, uint32_t b1) {
    asm volatile(
        "mma.sync.aligned.m16n8k16.row.col.f32.f16.f16.f32 "
        "{%0,%1,%2,%3}, {%4,%5,%6,%7}, {%8,%9}, {%0,%1,%2,%3};"
        : "+f"(c[0]), "+f"(c[1]), "+f"(c[2]), "+f"(c[3])
        : "r"(a[0]), "r"(a[1]), "r"(a[2]), "r"(a[3]), "r"(b0), "r"(b1));
}

// swizzle for 128B rows (GEMM tiles)
#define SWZ128(o) ((uint32_t)(o) ^ ((((uint32_t)(o)) >> 3) & 0x70u))

// ---------------- fp32 -> fp16 activations -----------------------------------
__global__ void cvt_kernel(const float* __restrict__ x,
                           __half* __restrict__ hi, int n)
{
    int i = blockIdx.x * blockDim.x + threadIdx.x;
    if (i >= n) return;
    hi[i] = __float2half_rn(x[i]);
}

// ---------------- pack W [H,D,F] and Hw^T into Bh [N=1536][K=768] fp16 -------
__global__ void prep_kernel(const float* __restrict__ W,
                            const float* __restrict__ Hw,
                            __half* __restrict__ bh)
{
    int idx = blockIdx.x * blockDim.x + threadIdx.x;
    if (idx >= GN * GK) return;
    int c = idx / GK;
    int k = idx - c * GK;
    float v;
    if (c < DD) {
        int hd = c / FF, f = c - hd * FF;
        v = W[((size_t)hd * GK + k) * FF + f];
    } else {
        v = Hw[(size_t)(c - DD) * GK + k];      // Hw^T
    }
    bh[idx] = __float2half_rn(v);
}

// ---------------- mma.sync GEMM: D[8192][1536] = A[8192][768] @ B^T ----------
// fp16 single-term. CTA 256x128, 512 thr (4x4 warps, warp tile 64x32).
// K-chunk 64 (SW128), 3-stage cp.async, depth-2 prefetch, 1 barrier/chunk.
#define KCH 64
#define A_STAGE 32768          /* 256 rows x 128B */
#define B_STAGE 16384          /* 128 rows x 128B */
#define STAGE_BYTES (A_STAGE + B_STAGE)
#define GEMM_SMEM (3*STAGE_BYTES)

__global__ __launch_bounds__(512, 1) void gemm_mma_kernel(
    const __half* __restrict__ Ah,
    const __half* __restrict__ Bh, const float* __restrict__ Hb)
{
    extern __shared__ char smem[];
    uint32_t sb = smem_u32(smem);

    int tid = threadIdx.x;
    int lane = tid & 31, wid = tid >> 5;
    int wm = wid >> 2, wn = wid & 3;           // 4(M) x 4(N) warps
    int bx = blockIdx.x, by = blockIdx.y;

    const __half* pa = Ah + (size_t)(by * 256) * GK;
    const __half* pb = Bh + (size_t)(bx * 128) * GK;

    // cp.async mapping: A 2 thr/row x 64B, B 4 thr/row x 32B
    int ra = tid >> 1, ha = tid & 1;
    int rb = tid >> 2, qb = tid & 3;
    uint32_t soA[4], soB[2];
#pragma unroll
    for (int i = 0; i < 4; i++)
        soA[i] = SWZ128((uint32_t)ra * 128 + (uint32_t)ha * 64 + (uint32_t)i * 16);
#pragma unroll
    for (int i = 0; i < 2; i++)
        soB[i] = SWZ128((uint32_t)rb * 128 + (uint32_t)qb * 32 + (uint32_t)i * 16);

    int sub = lane >> 3, sr = lane & 7;
    uint32_t offA0[4], offB0[2];
#pragma unroll
    for (int mt = 0; mt < 4; mt++)
        offA0[mt] = SWZ128((wm * 64 + mt * 16 + (sub & 1) * 8 + sr) * 128
                           + (sub >> 1) * 16);
#pragma unroll
    for (int nb = 0; nb < 2; nb++)
        offB0[nb] = SWZ128((wn * 32 + nb * 16 + (sub >> 1) * 8 + sr) * 128
                           + (sub & 1) * 16);

    float acc[4][4][4];
#pragma unroll
    for (int mt = 0; mt < 4; mt++)
#pragma unroll
        for (int j = 0; j < 4; j++)
#pragma unroll
            for (int e = 0; e < 4; e++) acc[mt][j][e] = 0.f;

#define GEMM_PF(st, kc) do {                                         \
        size_t offa = (size_t)ra * GK + (kc) + ha * 32;              \
        _Pragma("unroll")                                            \
        for (int i = 0; i < 4; i++)                                  \
            cpasync16((st) + soA[i], pa + offa + i * 8);             \
        size_t offb = (size_t)rb * GK + (kc) + qb * 16;              \
        _Pragma("unroll")                                            \
        for (int i = 0; i < 2; i++)                                  \
            cpasync16((st) + A_STAGE + soB[i], pb + offb + i * 8);   \
    } while (0)

    GEMM_PF(sb, 0);
    CP_COMMIT();
    GEMM_PF(sb + STAGE_BYTES, KCH);
    CP_COMMIT();

    const int NCHUNK = GK / KCH;     // 12
#pragma unroll 1
    for (int c = 0; c < NCHUNK; c++) {
        if (c + 1 < NCHUNK) { cp_wait<1>(); } else { cp_wait<0>(); }
        __syncthreads();
        if (c + 2 < NCHUNK) {
            GEMM_PF(sb + (uint32_t)((c + 2) % 3) * STAGE_BYTES, (c + 2) * KCH);
            CP_COMMIT();
        }

        uint32_t bs = sb + (uint32_t)(c % 3) * STAGE_BYTES;
#pragma unroll
        for (int ks = 0; ks < 4; ks++) {
            uint32_t kx = (uint32_t)ks << 5;   // SW128: col bits 5-6 XOR
            uint32_t aF[4][4], bF[2][4];
#pragma unroll
            for (int mt = 0; mt < 4; mt++)
                ldsm4(aF[mt], bs + (offA0[mt] ^ kx));
#pragma unroll
            for (int nb = 0; nb < 2; nb++)
                ldsm4(bF[nb], bs + A_STAGE + (offB0[nb] ^ kx));
#pragma unroll
            for (int mt = 0; mt < 4; mt++) {
#pragma unroll
                for (int j = 0; j < 4; j++) {
                    int nb = j >> 1, hf = (j & 1) * 2;
                    mma_f16(acc[mt][j], aF[mt], bF[nb][hf], bF[nb][hf + 1]);
                }
            }
        }
    }

    // ------------- epilogue: fp16-split h (half2) / sigmoid gate (float2) -----
    int g = lane >> 2, tig = lane & 3;
    int row_base = by * 256 + wm * 64;
    int col_base = bx * 128 + wn * 32;
    if (bx < 6) {
#pragma unroll
        for (int mt = 0; mt < 4; mt++) {
#pragma unroll
            for (int j = 0; j < 4; j++) {
                int col = col_base + j * 8 + tig * 2;   // even; pair never straddles hd
                int hd = col / FF, f = col - hd * FF;
                int rA = row_base + mt * 16 + g;
                int b0i = rA >> 9, n0i = rA & 511;
                size_t i0x = (((size_t)(b0i * HH + hd)) * NN + n0i) * FF + f;
                float v0 = acc[mt][j][0], v1 = acc[mt][j][1];
                __half h0 = __float2half_rn(v0), h1 = __float2half_rn(v1);
                *(__half2*)(g_hh + i0x) = __half2(h0, h1);
                *(__half2*)(g_hl + i0x) = __half2(
                    __float2half_rn(v0 - __half2float(h0)),
                    __float2half_rn(v1 - __half2float(h1)));
                int rB = rA + 8;
                int b1i = rB >> 9, n1i = rB & 511;
                size_t i1x = (((size_t)(b1i * HH + hd)) * NN + n1i) * FF + f;
                float w0 = acc[mt][j][2], w1 = acc[mt][j][3];
                __half k0 = __float2half_rn(w0), k1 = __float2half_rn(w1);
                *(__half2*)(g_hh + i1x) = __half2(k0, k1);
                *(__half2*)(g_hl + i1x) = __half2(
                    __float2half_rn(w0 - __half2float(k0)),
                    __float2half_rn(w1 - __half2float(k1)));
            }
        }
    } else {
        // gate stored SEMANTIC-LINEAR: g_gate[(b*N+n)*D + o]
#pragma unroll
        for (int mt = 0; mt < 4; mt++) {
#pragma unroll
            for (int j = 0; j < 4; j++) {
                int col = col_base + j * 8 + tig * 2;
                int o = col - DD;
                float hb0 = Hb[o], hb1 = Hb[o + 1];
                int rA = row_base + mt * 16 + g;
                float2 p0;
                p0.x = 1.f / (1.f + __expf(-(acc[mt][j][0] + hb0)));
                p0.y = 1.f / (1.f + __expf(-(acc[mt][j][1] + hb1)));
                *(float2*)(g_gate + (size_t)rA * DD + o) = p0;
                float2 p1;
                p1.x = 1.f / (1.f + __expf(-(acc[mt][j][2] + hb0)));
                p1.y = 1.f / (1.f + __expf(-(acc[mt][j][3] + hb1)));
                *(float2*)(g_gate + (size_t)(rA + 8) * DD + o) = p1;
            }
        }
    }
#undef GEMM_PF
}

// ---------------- s/d reductions + exp factors: one warp per (b,h,n) row -----
__global__ void sd_kernel(const float* __restrict__ asrc, const float* __restrict__ adst)
{
    int gtid = blockIdx.x * blockDim.x + threadIdx.x;
    int warp = gtid >> 5;
    int lane = gtid & 31;
    if (warp >= BB * HH * NN) return;
    int hd = (warp >> 9) & 7;
    const __half* rh = g_hh + (size_t)warp * FF;
    const __half* rl = g_hl + (size_t)warp * FF;
    float s = 0.f, d = 0.f;
#pragma unroll
    for (int k = 0; k < 3; k++) {
        int f = lane + k * 32;
        float t = tanhf(__half2float(rh[f]) + __half2float(rl[f]));
        s += t * asrc[hd * FF + f];
        d += t * adst[hd * FF + f];
    }
#pragma unroll
    for (int o = 16; o; o >>= 1) {
        s += __shfl_xor_sync(0xffffffffu, s, o);
        d += __shfl_xor_sync(0xffffffffu, d, o);
    }
    if (lane == 0) {
        g_es1[warp] = __expf(s);
        g_es2[warp] = __expf(0.2f * s);
        g_ed1[warp] = __expf(d);
        g_ed2[warp] = __expf(0.2f * d);
    }
}

// ---------------- tensor-core attention + FUSED coalesced epilogue -----------
// Output tile (hd,b,rows i0..i0+63, f 0..95) is flat-CONTIGUOUS in the
// scrambled output: stage o in smem, then sweep 6144 elements coalesced.
#define PPITCH 72     /* halfs; 144B rows */
#define HPITCH 104    /* halfs; 208B rows -> conflict-free ldmatrix.trans */
#define SPITCH 97     /* floats; stage pitch, conflict-free */
#define AT_E1 0
#define AT_E2 2048
#define AT_L  4096
#define AT_MX 4352
#define AT_PH 4608
#define AT_HH (AT_PH + 64*PPITCH*2)
#define AT_HL (AT_HH + 64*HPITCH*2)
#define ATTN_SMEM (AT_HL + 64*HPITCH*2)
// stage buffer reuses [AT_PH ...): needs 64*97*4 = 24832 B < available 45KB

__global__ __launch_bounds__(256) void attn_mma_kernel(
    const float* __restrict__ adj, const float* __restrict__ bias,
    const float* __restrict__ xin, float* __restrict__ yout,
    __half* __restrict__ yh)
{
    extern __shared__ char asm_buf[];
    float* shE1 = (float*)(asm_buf + AT_E1);
    float* shE2 = (float*)(asm_buf + AT_E2);
    float* shL  = (float*)(asm_buf + AT_L);
    float* shMx = (float*)(asm_buf + AT_MX);
    __half* sPh = (__half*)(asm_buf + AT_PH);
    uint32_t uHh = smem_u32(asm_buf + AT_HH);
    uint32_t uHl = smem_u32(asm_buf + AT_HL);

    int bh = blockIdx.x;
    int b = bh >> 3, hd = bh & 7;
    int i0 = blockIdx.y << 6;
    int tid = threadIdx.x, lane = tid & 31, wid = tid >> 5;
    int wm = wid >> 1, wn = wid & 1;

    float mloc = 0.f;
    for (int e = tid; e < NN; e += 256) {
        float v1 = g_ed1[(size_t)bh * NN + e];
        shE1[e] = v1;
        mloc = fmaxf(mloc, v1);
        shE2[e] = g_ed2[(size_t)bh * NN + e];
    }
#pragma unroll
    for (int o = 16; o; o >>= 1)
        mloc = fmaxf(mloc, __shfl_xor_sync(0xffffffffu, mloc, o));
    if (lane == 0) shMx[wid] = mloc;
    __syncthreads();
    float maxE1 = shMx[0];
#pragma unroll
    for (int w = 1; w < 8; w++) maxE1 = fmaxf(maxE1, shMx[w]);

    int si = tid >> 2, jg = tid & 3;
    float f1 = g_es1[(size_t)bh * NN + i0 + si];
    float f2 = g_es2[(size_t)bh * NN + i0 + si];
    float q1m = f1 * maxE1;
    float rsc = q1m > 1.f ? 1.f / q1m : 1.f;    // row scale (cancels in p/l)
    const float* adjrow = adj + ((size_t)b * NN + i0 + si) * NN;
    float lpriv = 0.f;

    int rA = wm * 16 + (lane >> 2);        // acc rows rA, rA+8
    float acc[6][4];
#pragma unroll
    for (int nt = 0; nt < 6; nt++)
#pragma unroll
        for (int e = 0; e < 4; e++) acc[nt][e] = 0.f;

    const __half* hbh = g_hh + (size_t)bh * NN * FF;
    const __half* hbl = g_hl + (size_t)bh * NN * FF;

    int kr_l = lane & 15;
    int nc_l = (lane >> 4) * 8;
    uint32_t aoff0 = (uint32_t)rA * (PPITCH * 2) + (uint32_t)(lane & 3) * 4;

    for (int jt = 0; jt < 8; jt++) {
        int j0 = jt << 6;
#pragma unroll
        for (int t = 0; t < 3; t++) {
            int cid = tid + t * 256;      // 0..767
            int row = cid / 12, c16 = cid % 12;
            uint32_t dst = (uint32_t)row * 208 + (uint32_t)c16 * 16;
            cpasync16(uHh + dst, hbh + (size_t)(j0 + row) * FF + c16 * 8);
            cpasync16(uHl + dst, hbl + (size_t)(j0 + row) * FF + c16 * 8);
        }
        CP_COMMIT();

        int jb = j0 + (jg << 4);
        const float4* arow4 = reinterpret_cast<const float4*>(adjrow + jb);
        float pv[16];
#pragma unroll
        for (int kk = 0; kk < 4; kk++) {
            float4 av = arow4[kk];
            float am[4] = {av.x, av.y, av.z, av.w};
#pragma unroll
            for (int e = 0; e < 4; e++) {
                int k = kk * 4 + e;
                float q1 = f1 * shE1[jb + k];
                float p = q1 > 1.f ? q1 : f2 * shE2[jb + k];
                p = am[e] > 0.f ? p * rsc : 0.f;
                pv[k] = p;
                lpriv += p;
            }
        }
        int pbase = si * PPITCH + (jg << 4);
#pragma unroll
        for (int k = 0; k < 16; k += 2) {
            __half2 h2;
            h2.x = __float2half_rn(pv[k]);
            h2.y = __float2half_rn(pv[k + 1]);
            *(__half2*)(sPh + pbase + k) = h2;
        }

        cp_wait<0>();
        __syncthreads();

#pragma unroll
        for (int ks = 0; ks < 4; ks++) {
            int k0 = ks * 16;
            uint32_t ah[4];
            {
                const char* ph = (const char*)sPh;
                uint32_t o = aoff0 + (uint32_t)k0 * 2;
                ah[0] = *(const uint32_t*)(ph + o);
                ah[1] = *(const uint32_t*)(ph + o + 8 * PPITCH * 2);
                ah[2] = *(const uint32_t*)(ph + o + 16);
                ah[3] = *(const uint32_t*)(ph + o + 8 * PPITCH * 2 + 16);
            }
#pragma unroll
            for (int np = 0; np < 3; np++) {
                int n0 = wn * 48 + np * 16;
                uint32_t boff = (uint32_t)(k0 + kr_l) * 208
                              + (uint32_t)(n0 + nc_l) * 2;
                uint32_t bH[4], bL[4];
                ldsm4t(bH, uHh + boff);
                ldsm4t(bL, uHl + boff);
                mma_f16(acc[np * 2],     ah, bH[0], bH[1]);
                mma_f16(acc[np * 2],     ah, bL[0], bL[1]);
                mma_f16(acc[np * 2 + 1], ah, bH[2], bH[3]);
                mma_f16(acc[np * 2 + 1], ah, bL[2], bL[3]);
            }
        }
        __syncthreads();
    }

    lpriv += __shfl_xor_sync(0xffffffffu, lpriv, 1);
    lpriv += __shfl_xor_sync(0xffffffffu, lpriv, 2);
    if (jg == 0) shL[si] = lpriv;
    __syncthreads();
    // invert l (warp 0..1 threads 0-63) while others start staging
    if (tid < 64) shL[tid] = 1.f / shL[tid];

    // -------- stage o tile into smem (conflict-free pitch 97) -----------------
    float* stg = (float*)(asm_buf + AT_PH);
#pragma unroll
    for (int nt = 0; nt < 6; nt++) {
        int col = wn * 48 + nt * 8 + (lane & 3) * 2;
        stg[rA * SPITCH + col]           = acc[nt][0];
        stg[rA * SPITCH + col + 1]       = acc[nt][1];
        stg[(rA + 8) * SPITCH + col]     = acc[nt][2];
        stg[(rA + 8) * SPITCH + col + 1] = acc[nt][3];
    }
    __syncthreads();

    // -------- coalesced combine over contiguous flat range --------------------
    size_t ob = (((size_t)hd * BB + b) * NN + i0) * FF;
#pragma unroll
    for (int k = 0; k < 24; k++) {
        int idx = tid + k * 256;            // 0..6143
        int row = idx / FF, colx = idx - row * FF;
        float o = stg[row * SPITCH + colx] * shL[row] + bias[colx];
        float e = o > 0.f ? o : expm1f(o);
        size_t I = ob + idx;
        float gt = g_gate[I];
        float y = gt * e + (1.f - gt) * xin[I];
        yout[I] = y;
        if (yh) yh[I] = __float2half_rn(y);
    }
}

// -----------------------------------------------------------------------------
extern "C" void kernel_launch(void* const* d_in, const int* in_sizes, int n_in,
                              void* d_out, int out_size)
{
    const float* emb = (const float*)d_in[0];
    const float* adj = (const float*)d_in[1];
    const float* W0  = (const float*)d_in[3];
    const float* b0  = (const float*)d_in[4];
    const float* as0 = (const float*)d_in[5];
    const float* ad0 = (const float*)d_in[6];
    const float* Hw0 = (const float*)d_in[7];
    const float* Hb0 = (const float*)d_in[8];
    const float* W1  = (const float*)d_in[9];
    const float* b1  = (const float*)d_in[10];
    const float* as1 = (const float*)d_in[11];
    const float* ad1 = (const float*)d_in[12];
    const float* Hw1 = (const float*)d_in[13];
    const float* Hb1 = (const float*)d_in[14];
    float* out = (float*)d_out;

    cudaFuncSetAttribute(gemm_mma_kernel,
                         cudaFuncAttributeMaxDynamicSharedMemorySize, GEMM_SMEM);
    cudaFuncSetAttribute(attn_mma_kernel,
                         cudaFuncAttributeMaxDynamicSharedMemorySize, ATTN_SMEM);

    void* p;
    cudaGetSymbolAddress(&p, g_x1);   float* x1  = (float*)p;
    cudaGetSymbolAddress(&p, g_Ah);   __half* ah  = (__half*)p;
    cudaGetSymbolAddress(&p, g_Bh);   __half* bh  = (__half*)p;

    int prep_blocks = (GN * GK + 255) / 256;
    prep_kernel<<<prep_blocks, 256>>>(W0, Hw0, bh);
    prep_kernel<<<prep_blocks, 256>>>(W1, Hw1, bh + (size_t)GN * GK);

    int cvt_blocks = (GM * GK + 255) / 256;
    dim3 gemm_grid(GN / 128, GM / 256);
    int sd_blocks = (BB * HH * NN * 32 + 255) / 256;
    dim3 attn_grid(BB * HH, NN / 64);

    // layer 0
    cvt_kernel<<<cvt_blocks, 256>>>(emb, ah, GM * GK);
    gemm_mma_kernel<<<gemm_grid, 512, GEMM_SMEM>>>(ah, bh, Hb0);
    sd_kernel<<<sd_blocks, 256>>>(as0, ad0);
    attn_mma_kernel<<<attn_grid, 256, ATTN_SMEM>>>(adj, b0, emb, x1, ah);

    // layer 1
    gemm_mma_kernel<<<gemm_grid, 512, GEMM_SMEM>>>(ah, bh + (size_t)GN * GK, Hb1);
    sd_kernel<<<sd_blocks, 256>>>(as1, ad1);
    attn_mma_kernel<<<attn_grid, 256, ATTN_SMEM>>>(adj, b1, x1, out, (__half*)0);
}

// round 15
// speedup vs baseline: 1.1671x; 1.1671x over previous
#include <cuda_runtime.h>
#include <cuda_fp16.h>
#include <math.h>
#include <stdint.h>

#define BB 16
#define NN 512
#define DD 768
#define HH 8
#define FF 96
#define GM (BB*NN)      /* 8192 rows */
#define GN (2*DD)       /* 1536 cols: [0,768)=h proj, [768,1536)=gate */
#define GK DD           /* 768 */

// ---------------- scratch (device globals; no allocs allowed) ----------------
__device__ __half g_hh[BB*HH*NN*FF];        // fp16 hi of h, [bh][n][f]
__device__ __half g_hl[BB*HH*NN*FF];        // fp16 lo of h
__device__ float g_att[BB*HH*NN*FF];        // [h][b][n][f]
__device__ float g_es1[BB*HH*NN];           // exp(s)
__device__ float g_es2[BB*HH*NN];           // exp(0.2 s)
__device__ float g_ed1[BB*HH*NN];           // exp(d)
__device__ float g_ed2[BB*HH*NN];           // exp(0.2 d)
__device__ float g_gate[BB*NN*DD];          // sigmoid already applied (linear)
__device__ float g_x1[BB*NN*DD];            // layer-0 output
__device__ __half g_Ah[GM*GK];              // fp16 activations
__device__ __half g_Bh[2][GN*GK];           // packed weights fp16 [N=1536][K=768]

// ============================ PTX helpers (base sm_103 only) =================
__device__ __forceinline__ uint32_t smem_u32(const void* p) {
    uint32_t a;
    asm("{ .reg .u64 t; cvta.to.shared.u64 t, %1; cvt.u32.u64 %0, t; }"
        : "=r"(a) : "l"(p));
    return a;
}

__device__ __forceinline__ void cpasync16(uint32_t saddr, const void* g) {
    asm volatile("cp.async.cg.shared.global [%0], [%1], 16;"
                 :: "r"(saddr), "l"(g) : "memory");
}
#define CP_COMMIT() asm volatile("cp.async.commit_group;" ::: "memory")
template<int N> __device__ __forceinline__ void cp_wait() {
    asm volatile("cp.async.wait_group %0;" :: "n"(N) : "memory");
}

__device__ __forceinline__ void ldsm4(uint32_t* r, uint32_t addr) {
    asm volatile("ldmatrix.sync.aligned.m8n8.x4.shared.b16 {%0,%1,%2,%3}, [%4];"
                 : "=r"(r[0]), "=r"(r[1]), "=r"(r[2]), "=r"(r[3]) : "r"(addr));
}
__device__ __forceinline__ void ldsm4t(uint32_t* r, uint32_t addr) {
    asm volatile("ldmatrix.sync.aligned.m8n8.x4.trans.shared.b16 {%0,%1,%2,%3}, [%4];"
                 : "=r"(r[0]), "=r"(r[1]), "=r"(r[2]), "=r"(r[3]) : "r"(addr));
}

__device__ __forceinline__ void mma_f16(float* c, const uint32_t* a,
                                        uint32_t b0, uint32_t b1) {
    asm volatile(
        "mma.sync.aligned.m16n8k16.row.col.f32.f16.f16.f32 "
        "{%0,%1,%2,%3}, {%4,%5,%6,%7}, {%8,%9}, {%0,%1,%2,%3};"
        : "+f"(c[0]), "+f"(c[1]), "+f"(c[2]), "+f"(c[3])
        : "r"(a[0]), "r"(a[1]), "r"(a[2]), "r"(a[3]), "r"(b0), "r"(b1));
}

// swizzle for 128B rows (GEMM tiles)
#define SWZ128(o) ((uint32_t)(o) ^ ((((uint32_t)(o)) >> 3) & 0x70u))

// ---------------- fp32 -> fp16 activations -----------------------------------
__global__ void cvt_kernel(const float* __restrict__ x,
                           __half* __restrict__ hi, int n)
{
    int i = blockIdx.x * blockDim.x + threadIdx.x;
    if (i >= n) return;
    hi[i] = __float2half_rn(x[i]);
}

// ---------------- pack W [H,D,F] and Hw^T into Bh [N=1536][K=768] fp16 -------
__global__ void prep_kernel(const float* __restrict__ W,
                            const float* __restrict__ Hw,
                            __half* __restrict__ bh)
{
    int idx = blockIdx.x * blockDim.x + threadIdx.x;
    if (idx >= GN * GK) return;
    int c = idx / GK;
    int k = idx - c * GK;
    float v;
    if (c < DD) {
        int hd = c / FF, f = c - hd * FF;
        v = W[((size_t)hd * GK + k) * FF + f];
    } else {
        v = Hw[(size_t)(c - DD) * GK + k];      // Hw^T
    }
    bh[idx] = __float2half_rn(v);
}

// ---------------- mma.sync GEMM: D[8192][1536] = A[8192][768] @ B^T ----------
// fp16 single-term. CTA 256x128, 512 thr (4x4 warps, warp tile 64x32).
// K-chunk 64 (SW128), 3-stage cp.async, depth-2 prefetch, 1 barrier/chunk.
// Vectorized epilogue (half2 / float2 stores).
#define KCH 64
#define A_STAGE 32768          /* 256 rows x 128B */
#define B_STAGE 16384          /* 128 rows x 128B */
#define STAGE_BYTES (A_STAGE + B_STAGE)
#define GEMM_SMEM (3*STAGE_BYTES)

__global__ __launch_bounds__(512, 1) void gemm_mma_kernel(
    const __half* __restrict__ Ah,
    const __half* __restrict__ Bh, const float* __restrict__ Hb)
{
    extern __shared__ char smem[];
    uint32_t sb = smem_u32(smem);

    int tid = threadIdx.x;
    int lane = tid & 31, wid = tid >> 5;
    int wm = wid >> 2, wn = wid & 3;           // 4(M) x 4(N) warps
    int bx = blockIdx.x, by = blockIdx.y;

    const __half* pa = Ah + (size_t)(by * 256) * GK;
    const __half* pb = Bh + (size_t)(bx * 128) * GK;

    int ra = tid >> 1, ha = tid & 1;
    int rb = tid >> 2, qb = tid & 3;
    uint32_t soA[4], soB[2];
#pragma unroll
    for (int i = 0; i < 4; i++)
        soA[i] = SWZ128((uint32_t)ra * 128 + (uint32_t)ha * 64 + (uint32_t)i * 16);
#pragma unroll
    for (int i = 0; i < 2; i++)
        soB[i] = SWZ128((uint32_t)rb * 128 + (uint32_t)qb * 32 + (uint32_t)i * 16);

    int sub = lane >> 3, sr = lane & 7;
    uint32_t offA0[4], offB0[2];
#pragma unroll
    for (int mt = 0; mt < 4; mt++)
        offA0[mt] = SWZ128((wm * 64 + mt * 16 + (sub & 1) * 8 + sr) * 128
                           + (sub >> 1) * 16);
#pragma unroll
    for (int nb = 0; nb < 2; nb++)
        offB0[nb] = SWZ128((wn * 32 + nb * 16 + (sub >> 1) * 8 + sr) * 128
                           + (sub & 1) * 16);

    float acc[4][4][4];
#pragma unroll
    for (int mt = 0; mt < 4; mt++)
#pragma unroll
        for (int j = 0; j < 4; j++)
#pragma unroll
            for (int e = 0; e < 4; e++) acc[mt][j][e] = 0.f;

#define GEMM_PF(st, kc) do {                                         \
        size_t offa = (size_t)ra * GK + (kc) + ha * 32;              \
        _Pragma("unroll")                                            \
        for (int i = 0; i < 4; i++)                                  \
            cpasync16((st) + soA[i], pa + offa + i * 8);             \
        size_t offb = (size_t)rb * GK + (kc) + qb * 16;              \
        _Pragma("unroll")                                            \
        for (int i = 0; i < 2; i++)                                  \
            cpasync16((st) + A_STAGE + soB[i], pb + offb + i * 8);   \
    } while (0)

    GEMM_PF(sb, 0);
    CP_COMMIT();
    GEMM_PF(sb + STAGE_BYTES, KCH);
    CP_COMMIT();

    const int NCHUNK = GK / KCH;     // 12
#pragma unroll 1
    for (int c = 0; c < NCHUNK; c++) {
        if (c + 1 < NCHUNK) { cp_wait<1>(); } else { cp_wait<0>(); }
        __syncthreads();
        if (c + 2 < NCHUNK) {
            GEMM_PF(sb + (uint32_t)((c + 2) % 3) * STAGE_BYTES, (c + 2) * KCH);
            CP_COMMIT();
        }

        uint32_t bs = sb + (uint32_t)(c % 3) * STAGE_BYTES;
#pragma unroll
        for (int ks = 0; ks < 4; ks++) {
            uint32_t kx = (uint32_t)ks << 5;   // SW128: col bits 5-6 XOR
            uint32_t aF[4][4], bF[2][4];
#pragma unroll
            for (int mt = 0; mt < 4; mt++)
                ldsm4(aF[mt], bs + (offA0[mt] ^ kx));
#pragma unroll
            for (int nb = 0; nb < 2; nb++)
                ldsm4(bF[nb], bs + A_STAGE + (offB0[nb] ^ kx));
#pragma unroll
            for (int mt = 0; mt < 4; mt++) {
#pragma unroll
                for (int j = 0; j < 4; j++) {
                    int nb = j >> 1, hf = (j & 1) * 2;
                    mma_f16(acc[mt][j], aF[mt], bF[nb][hf], bF[nb][hf + 1]);
                }
            }
        }
    }

    // ------------- epilogue: fp16-split h (half2) / sigmoid gate (float2) -----
    int g = lane >> 2, tig = lane & 3;
    int row_base = by * 256 + wm * 64;
    int col_base = bx * 128 + wn * 32;
    if (bx < 6) {
#pragma unroll
        for (int mt = 0; mt < 4; mt++) {
#pragma unroll
            for (int j = 0; j < 4; j++) {
                int col = col_base + j * 8 + tig * 2;   // even; pair never straddles hd
                int hd = col / FF, f = col - hd * FF;
                int rA = row_base + mt * 16 + g;
                int b0i = rA >> 9, n0i = rA & 511;
                size_t i0x = (((size_t)(b0i * HH + hd)) * NN + n0i) * FF + f;
                float v0 = acc[mt][j][0], v1 = acc[mt][j][1];
                __half h0 = __float2half_rn(v0), h1 = __float2half_rn(v1);
                *(__half2*)(g_hh + i0x) = __half2(h0, h1);
                *(__half2*)(g_hl + i0x) = __half2(
                    __float2half_rn(v0 - __half2float(h0)),
                    __float2half_rn(v1 - __half2float(h1)));
                int rB = rA + 8;
                int b1i = rB >> 9, n1i = rB & 511;
                size_t i1x = (((size_t)(b1i * HH + hd)) * NN + n1i) * FF + f;
                float w0 = acc[mt][j][2], w1 = acc[mt][j][3];
                __half k0 = __float2half_rn(w0), k1 = __float2half_rn(w1);
                *(__half2*)(g_hh + i1x) = __half2(k0, k1);
                *(__half2*)(g_hl + i1x) = __half2(
                    __float2half_rn(w0 - __half2float(k0)),
                    __float2half_rn(w1 - __half2float(k1)));
            }
        }
    } else {
        // gate stored SEMANTIC-LINEAR: g_gate[(b*N+n)*D + o]
#pragma unroll
        for (int mt = 0; mt < 4; mt++) {
#pragma unroll
            for (int j = 0; j < 4; j++) {
                int col = col_base + j * 8 + tig * 2;
                int o = col - DD;
                float hb0 = Hb[o], hb1 = Hb[o + 1];
                int rA = row_base + mt * 16 + g;
                float2 p0;
                p0.x = 1.f / (1.f + __expf(-(acc[mt][j][0] + hb0)));
                p0.y = 1.f / (1.f + __expf(-(acc[mt][j][1] + hb1)));
                *(float2*)(g_gate + (size_t)rA * DD + o) = p0;
                float2 p1;
                p1.x = 1.f / (1.f + __expf(-(acc[mt][j][2] + hb0)));
                p1.y = 1.f / (1.f + __expf(-(acc[mt][j][3] + hb1)));
                *(float2*)(g_gate + (size_t)(rA + 8) * DD + o) = p1;
            }
        }
    }
#undef GEMM_PF
}

// ---------------- s/d reductions + exp factors: one warp per (b,h,n) row -----
__global__ void sd_kernel(const float* __restrict__ asrc, const float* __restrict__ adst)
{
    int gtid = blockIdx.x * blockDim.x + threadIdx.x;
    int warp = gtid >> 5;
    int lane = gtid & 31;
    if (warp >= BB * HH * NN) return;
    int hd = (warp >> 9) & 7;
    const __half* rh = g_hh + (size_t)warp * FF;
    const __half* rl = g_hl + (size_t)warp * FF;
    float s = 0.f, d = 0.f;
#pragma unroll
    for (int k = 0; k < 3; k++) {
        int f = lane + k * 32;
        float t = tanhf(__half2float(rh[f]) + __half2float(rl[f]));
        s += t * asrc[hd * FF + f];
        d += t * adst[hd * FF + f];
    }
#pragma unroll
    for (int o = 16; o; o >>= 1) {
        s += __shfl_xor_sync(0xffffffffu, s, o);
        d += __shfl_xor_sync(0xffffffffu, d, o);
    }
    if (lane == 0) {
        g_es1[warp] = __expf(s);
        g_es2[warp] = __expf(0.2f * s);
        g_ed1[warp] = __expf(d);
        g_ed2[warp] = __expf(0.2f * d);
    }
}

// ---------------- tensor-core attention, one-pass softmax (R10 version) ------
#define PPITCH 72     /* halfs; 144B rows */
#define HPITCH 104    /* halfs; 208B rows -> conflict-free ldmatrix.trans */
#define AT_E1 0
#define AT_E2 2048
#define AT_L  4096
#define AT_MX 4352
#define AT_PH 4608
#define AT_HH (AT_PH + 64*PPITCH*2)
#define AT_HL (AT_HH + 64*HPITCH*2)
#define ATTN_SMEM (AT_HL + 64*HPITCH*2)

__global__ __launch_bounds__(256) void attn_mma_kernel(
    const float* __restrict__ adj, const float* __restrict__ bias)
{
    extern __shared__ char asm_buf[];
    float* shE1 = (float*)(asm_buf + AT_E1);
    float* shE2 = (float*)(asm_buf + AT_E2);
    float* shL  = (float*)(asm_buf + AT_L);
    float* shMx = (float*)(asm_buf + AT_MX);
    __half* sPh = (__half*)(asm_buf + AT_PH);
    uint32_t uHh = smem_u32(asm_buf + AT_HH);
    uint32_t uHl = smem_u32(asm_buf + AT_HL);

    int bh = blockIdx.x;
    int b = bh >> 3, hd = bh & 7;
    int i0 = blockIdx.y << 6;
    int tid = threadIdx.x, lane = tid & 31, wid = tid >> 5;
    int wm = wid >> 1, wn = wid & 1;

    float mloc = 0.f;
    for (int e = tid; e < NN; e += 256) {
        float v1 = g_ed1[(size_t)bh * NN + e];
        shE1[e] = v1;
        mloc = fmaxf(mloc, v1);
        shE2[e] = g_ed2[(size_t)bh * NN + e];
    }
#pragma unroll
    for (int o = 16; o; o >>= 1)
        mloc = fmaxf(mloc, __shfl_xor_sync(0xffffffffu, mloc, o));
    if (lane == 0) shMx[wid] = mloc;
    __syncthreads();
    float maxE1 = shMx[0];
#pragma unroll
    for (int w = 1; w < 8; w++) maxE1 = fmaxf(maxE1, shMx[w]);

    int si = tid >> 2, jg = tid & 3;
    float f1 = g_es1[(size_t)bh * NN + i0 + si];
    float f2 = g_es2[(size_t)bh * NN + i0 + si];
    float q1m = f1 * maxE1;
    float rsc = q1m > 1.f ? 1.f / q1m : 1.f;    // row scale (cancels in p/l)
    const float* adjrow = adj + ((size_t)b * NN + i0 + si) * NN;
    float lpriv = 0.f;

    int rA = wm * 16 + (lane >> 2);        // acc rows rA, rA+8
    float acc[6][4];
#pragma unroll
    for (int nt = 0; nt < 6; nt++)
#pragma unroll
        for (int e = 0; e < 4; e++) acc[nt][e] = 0.f;

    const __half* hbh = g_hh + (size_t)bh * NN * FF;
    const __half* hbl = g_hl + (size_t)bh * NN * FF;

    int kr_l = lane & 15;
    int nc_l = (lane >> 4) * 8;
    uint32_t aoff0 = (uint32_t)rA * (PPITCH * 2) + (uint32_t)(lane & 3) * 4;

    for (int jt = 0; jt < 8; jt++) {
        int j0 = jt << 6;
#pragma unroll
        for (int t = 0; t < 3; t++) {
            int cid = tid + t * 256;      // 0..767
            int row = cid / 12, c16 = cid % 12;
            uint32_t dst = (uint32_t)row * 208 + (uint32_t)c16 * 16;
            cpasync16(uHh + dst, hbh + (size_t)(j0 + row) * FF + c16 * 8);
            cpasync16(uHl + dst, hbl + (size_t)(j0 + row) * FF + c16 * 8);
        }
        CP_COMMIT();

        int jb = j0 + (jg << 4);
        const float4* arow4 = reinterpret_cast<const float4*>(adjrow + jb);
        float pv[16];
#pragma unroll
        for (int kk = 0; kk < 4; kk++) {
            float4 av = arow4[kk];
            float am[4] = {av.x, av.y, av.z, av.w};
#pragma unroll
            for (int e = 0; e < 4; e++) {
                int k = kk * 4 + e;
                float q1 = f1 * shE1[jb + k];
                float p = q1 > 1.f ? q1 : f2 * shE2[jb + k];
                p = am[e] > 0.f ? p * rsc : 0.f;
                pv[k] = p;
                lpriv += p;
            }
        }
        int pbase = si * PPITCH + (jg << 4);
#pragma unroll
        for (int k = 0; k < 16; k += 2) {
            __half2 h2;
            h2.x = __float2half_rn(pv[k]);
            h2.y = __float2half_rn(pv[k + 1]);
            *(__half2*)(sPh + pbase + k) = h2;
        }

        cp_wait<0>();
        __syncthreads();

#pragma unroll
        for (int ks = 0; ks < 4; ks++) {
            int k0 = ks * 16;
            uint32_t ah[4];
            {
                const char* ph = (const char*)sPh;
                uint32_t o = aoff0 + (uint32_t)k0 * 2;
                ah[0] = *(const uint32_t*)(ph + o);
                ah[1] = *(const uint32_t*)(ph + o + 8 * PPITCH * 2);
                ah[2] = *(const uint32_t*)(ph + o + 16);
                ah[3] = *(const uint32_t*)(ph + o + 8 * PPITCH * 2 + 16);
            }
#pragma unroll
            for (int np = 0; np < 3; np++) {
                int n0 = wn * 48 + np * 16;
                uint32_t boff = (uint32_t)(k0 + kr_l) * 208
                              + (uint32_t)(n0 + nc_l) * 2;
                uint32_t bH[4], bL[4];
                ldsm4t(bH, uHh + boff);
                ldsm4t(bL, uHl + boff);
                mma_f16(acc[np * 2],     ah, bH[0], bH[1]);
                mma_f16(acc[np * 2],     ah, bL[0], bL[1]);
                mma_f16(acc[np * 2 + 1], ah, bH[2], bH[3]);
                mma_f16(acc[np * 2 + 1], ah, bL[2], bL[3]);
            }
        }
        __syncthreads();
    }

    lpriv += __shfl_xor_sync(0xffffffffu, lpriv, 1);
    lpriv += __shfl_xor_sync(0xffffffffu, lpriv, 2);
    if (jg == 0) shL[si] = lpriv;
    __syncthreads();

    float inv1 = 1.f / shL[rA];
    float inv2 = 1.f / shL[rA + 8];
    size_t ob = (((size_t)hd * BB + b) * NN + i0) * FF;
#pragma unroll
    for (int nt = 0; nt < 6; nt++) {
        int col = wn * 48 + nt * 8 + (lane & 3) * 2;
        float b0v = bias[col], b1v = bias[col + 1];
        float2 o1; o1.x = acc[nt][0] * inv1 + b0v; o1.y = acc[nt][1] * inv1 + b1v;
        *(float2*)(g_att + ob + (size_t)rA * FF + col) = o1;
        float2 o2; o2.x = acc[nt][2] * inv2 + b0v; o2.y = acc[nt][3] * inv2 + b1v;
        *(float2*)(g_att + ob + (size_t)(rA + 8) * FF + col) = o2;
    }
}

// ---------------- y = gate*elu(att) + (1-gate)*x (+ optional fp16 out) -------
__global__ void combine_split_kernel(const float* __restrict__ xin,
                                     float* __restrict__ yout,
                                     __half* __restrict__ hi)
{
    int i = blockIdx.x * blockDim.x + threadIdx.x;
    if (i >= BB * NN * DD) return;
    float a = g_att[i];
    float e = a > 0.f ? a : expm1f(a);
    float g = g_gate[i];
    float y = g * e + (1.f - g) * xin[i];
    yout[i] = y;
    hi[i] = __float2half_rn(y);
}

__global__ void combine_kernel(const float* __restrict__ xin, float* __restrict__ yout)
{
    int i = blockIdx.x * blockDim.x + threadIdx.x;
    if (i >= BB * NN * DD) return;
    float a = g_att[i];
    float e = a > 0.f ? a : expm1f(a);
    float g = g_gate[i];
    yout[i] = g * e + (1.f - g) * xin[i];
}

// -----------------------------------------------------------------------------
extern "C" void kernel_launch(void* const* d_in, const int* in_sizes, int n_in,
                              void* d_out, int out_size)
{
    const float* emb = (const float*)d_in[0];
    const float* adj = (const float*)d_in[1];
    const float* W0  = (const float*)d_in[3];
    const float* b0  = (const float*)d_in[4];
    const float* as0 = (const float*)d_in[5];
    const float* ad0 = (const float*)d_in[6];
    const float* Hw0 = (const float*)d_in[7];
    const float* Hb0 = (const float*)d_in[8];
    const float* W1  = (const float*)d_in[9];
    const float* b1  = (const float*)d_in[10];
    const float* as1 = (const float*)d_in[11];
    const float* ad1 = (const float*)d_in[12];
    const float* Hw1 = (const float*)d_in[13];
    const float* Hb1 = (const float*)d_in[14];
    float* out = (float*)d_out;

    cudaFuncSetAttribute(gemm_mma_kernel,
                         cudaFuncAttributeMaxDynamicSharedMemorySize, GEMM_SMEM);
    cudaFuncSetAttribute(attn_mma_kernel,
                         cudaFuncAttributeMaxDynamicSharedMemorySize, ATTN_SMEM);

    void* p;
    cudaGetSymbolAddress(&p, g_x1);   float* x1  = (float*)p;
    cudaGetSymbolAddress(&p, g_Ah);   __half* ah  = (__half*)p;
    cudaGetSymbolAddress(&p, g_Bh);   __half* bh  = (__half*)p;

    int prep_blocks = (GN * GK + 255) / 256;
    prep_kernel<<<prep_blocks, 256>>>(W0, Hw0, bh);
    prep_kernel<<<prep_blocks, 256>>>(W1, Hw1, bh + (size_t)GN * GK);

    int cvt_blocks = (GM * GK + 255) / 256;
    dim3 gemm_grid(GN / 128, GM / 256);
    int sd_blocks = (BB * HH * NN * 32 + 255) / 256;
    dim3 attn_grid(BB * HH, NN / 64);
    int cmb_blocks = (BB * NN * DD + 255) / 256;

    // layer 0
    cvt_kernel<<<cvt_blocks, 256>>>(emb, ah, GM * GK);
    gemm_mma_kernel<<<gemm_grid, 512, GEMM_SMEM>>>(ah, bh, Hb0);
    sd_kernel<<<sd_blocks, 256>>>(as0, ad0);
    attn_mma_kernel<<<attn_grid, 256, ATTN_SMEM>>>(adj, b0);
    combine_split_kernel<<<cmb_blocks, 256>>>(emb, x1, ah);

    // layer 1
    gemm_mma_kernel<<<gemm_grid, 512, GEMM_SMEM>>>(ah, bh + (size_t)GN * GK, Hb1);
    sd_kernel<<<sd_blocks, 256>>>(as1, ad1);
    attn_mma_kernel<<<attn_grid, 256, ATTN_SMEM>>>(adj, b1);
    combine_kernel<<<cmb_blocks, 256>>>(x1, out);
}

// round 16
// speedup vs baseline: 1.3265x; 1.1366x over previous
#include <cuda_runtime.h>
#include <cuda_fp16.h>
#include <math.h>
#include <stdint.h>

#define BB 16
#define NN 512
#define DD 768
#define HH 8
#define FF 96
#define GM (BB*NN)      /* 8192 rows */
#define GN (2*DD)       /* 1536 cols: [0,768)=h proj, [768,1536)=gate */
#define GK DD           /* 768 */

// ---------------- scratch (device globals; no allocs allowed) ----------------
__device__ __half g_hh[BB*HH*NN*FF];        // fp16 h, [bh][n][f]
__device__ float g_att[BB*HH*NN*FF];        // [h][b][n][f]
__device__ float g_es1[BB*HH*NN];           // exp(s)
__device__ float g_es2[BB*HH*NN];           // exp(0.2 s)
__device__ float g_ed1[BB*HH*NN];           // exp(d)
__device__ float g_ed2[BB*HH*NN];           // exp(0.2 d)
__device__ float g_gate[BB*NN*DD];          // sigmoid already applied (linear)
__device__ float g_x1[BB*NN*DD];            // layer-0 output
__device__ __half g_Ah[GM*GK];              // fp16 activations
__device__ __half g_Bh[2][GN*GK];           // packed weights fp16 [N=1536][K=768]

// ============================ PTX helpers (base sm_103 only) =================
__device__ __forceinline__ uint32_t smem_u32(const void* p) {
    uint32_t a;
    asm("{ .reg .u64 t; cvta.to.shared.u64 t, %1; cvt.u32.u64 %0, t; }"
        : "=r"(a) : "l"(p));
    return a;
}

__device__ __forceinline__ void cpasync16(uint32_t saddr, const void* g) {
    asm volatile("cp.async.cg.shared.global [%0], [%1], 16;"
                 :: "r"(saddr), "l"(g) : "memory");
}
#define CP_COMMIT() asm volatile("cp.async.commit_group;" ::: "memory")
template<int N> __device__ __forceinline__ void cp_wait() {
    asm volatile("cp.async.wait_group %0;" :: "n"(N) : "memory");
}

__device__ __forceinline__ void ldsm4(uint32_t* r, uint32_t addr) {
    asm volatile("ldmatrix.sync.aligned.m8n8.x4.shared.b16 {%0,%1,%2,%3}, [%4];"
                 : "=r"(r[0]), "=r"(r[1]), "=r"(r[2]), "=r"(r[3]) : "r"(addr));
}
__device__ __forceinline__ void ldsm4t(uint32_t* r, uint32_t addr) {
    asm volatile("ldmatrix.sync.aligned.m8n8.x4.trans.shared.b16 {%0,%1,%2,%3}, [%4];"
                 : "=r"(r[0]), "=r"(r[1]), "=r"(r[2]), "=r"(r[3]) : "r"(addr));
}

__device__ __forceinline__ void mma_f16(float* c, const uint32_t* a,
                                        uint32_t b0, uint32_t b1) {
    asm volatile(
        "mma.sync.aligned.m16n8k16.row.col.f32.f16.f16.f32 "
        "{%0,%1,%2,%3}, {%4,%5,%6,%7}, {%8,%9}, {%0,%1,%2,%3};"
        : "+f"(c[0]), "+f"(c[1]), "+f"(c[2]), "+f"(c[3])
        : "r"(a[0]), "r"(a[1]), "r"(a[2]), "r"(a[3]), "r"(b0), "r"(b1));
}

// swizzle for 128B rows (GEMM tiles)
#define SWZ128(o) ((uint32_t)(o) ^ ((((uint32_t)(o)) >> 3) & 0x70u))

// ---------------- fp32 -> fp16 activations -----------------------------------
__global__ void cvt_kernel(const float* __restrict__ x,
                           __half* __restrict__ hi, int n)
{
    int i = blockIdx.x * blockDim.x + threadIdx.x;
    if (i >= n) return;
    hi[i] = __float2half_rn(x[i]);
}

// ---------------- pack W [H,D,F] and Hw^T into Bh [N=1536][K=768] fp16 -------
__global__ void prep_kernel(const float* __restrict__ W,
                            const float* __restrict__ Hw,
                            __half* __restrict__ bh)
{
    int idx = blockIdx.x * blockDim.x + threadIdx.x;
    if (idx >= GN * GK) return;
    int c = idx / GK;
    int k = idx - c * GK;
    float v;
    if (c < DD) {
        int hd = c / FF, f = c - hd * FF;
        v = W[((size_t)hd * GK + k) * FF + f];
    } else {
        v = Hw[(size_t)(c - DD) * GK + k];      // Hw^T
    }
    bh[idx] = __float2half_rn(v);
}

// ---------------- mma.sync GEMM: D[8192][1536] = A[8192][768] @ B^T ----------
// fp16 single-term. CTA 256x128, 512 thr (4x4 warps, warp tile 64x32).
// K-chunk 64 (SW128), 3-stage cp.async, depth-2 prefetch, 1 barrier/chunk.
// Vectorized epilogue (half2 / float2 stores).
#define KCH 64
#define A_STAGE 32768          /* 256 rows x 128B */
#define B_STAGE 16384          /* 128 rows x 128B */
#define STAGE_BYTES (A_STAGE + B_STAGE)
#define GEMM_SMEM (3*STAGE_BYTES)

__global__ __launch_bounds__(512, 1) void gemm_mma_kernel(
    const __half* __restrict__ Ah,
    const __half* __restrict__ Bh, const float* __restrict__ Hb)
{
    extern __shared__ char smem[];
    uint32_t sb = smem_u32(smem);

    int tid = threadIdx.x;
    int lane = tid & 31, wid = tid >> 5;
    int wm = wid >> 2, wn = wid & 3;           // 4(M) x 4(N) warps
    int bx = blockIdx.x, by = blockIdx.y;

    const __half* pa = Ah + (size_t)(by * 256) * GK;
    const __half* pb = Bh + (size_t)(bx * 128) * GK;

    int ra = tid >> 1, ha = tid & 1;
    int rb = tid >> 2, qb = tid & 3;
    uint32_t soA[4], soB[2];
#pragma unroll
    for (int i = 0; i < 4; i++)
        soA[i] = SWZ128((uint32_t)ra * 128 + (uint32_t)ha * 64 + (uint32_t)i * 16);
#pragma unroll
    for (int i = 0; i < 2; i++)
        soB[i] = SWZ128((uint32_t)rb * 128 + (uint32_t)qb * 32 + (uint32_t)i * 16);

    int sub = lane >> 3, sr = lane & 7;
    uint32_t offA0[4], offB0[2];
#pragma unroll
    for (int mt = 0; mt < 4; mt++)
        offA0[mt] = SWZ128((wm * 64 + mt * 16 + (sub & 1) * 8 + sr) * 128
                           + (sub >> 1) * 16);
#pragma unroll
    for (int nb = 0; nb < 2; nb++)
        offB0[nb] = SWZ128((wn * 32 + nb * 16 + (sub >> 1) * 8 + sr) * 128
                           + (sub & 1) * 16);

    float acc[4][4][4];
#pragma unroll
    for (int mt = 0; mt < 4; mt++)
#pragma unroll
        for (int j = 0; j < 4; j++)
#pragma unroll
            for (int e = 0; e < 4; e++) acc[mt][j][e] = 0.f;

#define GEMM_PF(st, kc) do {                                         \
        size_t offa = (size_t)ra * GK + (kc) + ha * 32;              \
        _Pragma("unroll")                                            \
        for (int i = 0; i < 4; i++)                                  \
            cpasync16((st) + soA[i], pa + offa + i * 8);             \
        size_t offb = (size_t)rb * GK + (kc) + qb * 16;              \
        _Pragma("unroll")                                            \
        for (int i = 0; i < 2; i++)                                  \
            cpasync16((st) + A_STAGE + soB[i], pb + offb + i * 8);   \
    } while (0)

    GEMM_PF(sb, 0);
    CP_COMMIT();
    GEMM_PF(sb + STAGE_BYTES, KCH);
    CP_COMMIT();

    const int NCHUNK = GK / KCH;     // 12
#pragma unroll 1
    for (int c = 0; c < NCHUNK; c++) {
        if (c + 1 < NCHUNK) { cp_wait<1>(); } else { cp_wait<0>(); }
        __syncthreads();
        if (c + 2 < NCHUNK) {
            GEMM_PF(sb + (uint32_t)((c + 2) % 3) * STAGE_BYTES, (c + 2) * KCH);
            CP_COMMIT();
        }

        uint32_t bs = sb + (uint32_t)(c % 3) * STAGE_BYTES;
#pragma unroll
        for (int ks = 0; ks < 4; ks++) {
            uint32_t kx = (uint32_t)ks << 5;   // SW128: col bits 5-6 XOR
            uint32_t aF[4][4], bF[2][4];
#pragma unroll
            for (int mt = 0; mt < 4; mt++)
                ldsm4(aF[mt], bs + (offA0[mt] ^ kx));
#pragma unroll
            for (int nb = 0; nb < 2; nb++)
                ldsm4(bF[nb], bs + A_STAGE + (offB0[nb] ^ kx));
#pragma unroll
            for (int mt = 0; mt < 4; mt++) {
#pragma unroll
                for (int j = 0; j < 4; j++) {
                    int nb = j >> 1, hf = (j & 1) * 2;
                    mma_f16(acc[mt][j], aF[mt], bF[nb][hf], bF[nb][hf + 1]);
                }
            }
        }
    }

    // ------------- epilogue: fp16 h (half2) / sigmoid gate (float2) -----------
    int g = lane >> 2, tig = lane & 3;
    int row_base = by * 256 + wm * 64;
    int col_base = bx * 128 + wn * 32;
    if (bx < 6) {
#pragma unroll
        for (int mt = 0; mt < 4; mt++) {
#pragma unroll
            for (int j = 0; j < 4; j++) {
                int col = col_base + j * 8 + tig * 2;   // even; pair never straddles hd
                int hd = col / FF, f = col - hd * FF;
                int rA = row_base + mt * 16 + g;
                int b0i = rA >> 9, n0i = rA & 511;
                size_t i0x = (((size_t)(b0i * HH + hd)) * NN + n0i) * FF + f;
                *(__half2*)(g_hh + i0x) = __half2(
                    __float2half_rn(acc[mt][j][0]), __float2half_rn(acc[mt][j][1]));
                int rB = rA + 8;
                int b1i = rB >> 9, n1i = rB & 511;
                size_t i1x = (((size_t)(b1i * HH + hd)) * NN + n1i) * FF + f;
                *(__half2*)(g_hh + i1x) = __half2(
                    __float2half_rn(acc[mt][j][2]), __float2half_rn(acc[mt][j][3]));
            }
        }
    } else {
        // gate stored SEMANTIC-LINEAR: g_gate[(b*N+n)*D + o]
#pragma unroll
        for (int mt = 0; mt < 4; mt++) {
#pragma unroll
            for (int j = 0; j < 4; j++) {
                int col = col_base + j * 8 + tig * 2;
                int o = col - DD;
                float hb0 = Hb[o], hb1 = Hb[o + 1];
                int rA = row_base + mt * 16 + g;
                float2 p0;
                p0.x = 1.f / (1.f + __expf(-(acc[mt][j][0] + hb0)));
                p0.y = 1.f / (1.f + __expf(-(acc[mt][j][1] + hb1)));
                *(float2*)(g_gate + (size_t)rA * DD + o) = p0;
                float2 p1;
                p1.x = 1.f / (1.f + __expf(-(acc[mt][j][2] + hb0)));
                p1.y = 1.f / (1.f + __expf(-(acc[mt][j][3] + hb1)));
                *(float2*)(g_gate + (size_t)(rA + 8) * DD + o) = p1;
            }
        }
    }
#undef GEMM_PF
}

// ---------------- s/d reductions + exp factors: one warp per (b,h,n) row -----
__global__ void sd_kernel(const float* __restrict__ asrc, const float* __restrict__ adst)
{
    int gtid = blockIdx.x * blockDim.x + threadIdx.x;
    int warp = gtid >> 5;
    int lane = gtid & 31;
    if (warp >= BB * HH * NN) return;
    int hd = (warp >> 9) & 7;
    const __half* rh = g_hh + (size_t)warp * FF;
    float s = 0.f, d = 0.f;
#pragma unroll
    for (int k = 0; k < 3; k++) {
        int f = lane + k * 32;
        float t = tanhf(__half2float(rh[f]));
        s += t * asrc[hd * FF + f];
        d += t * adst[hd * FF + f];
    }
#pragma unroll
    for (int o = 16; o; o >>= 1) {
        s += __shfl_xor_sync(0xffffffffu, s, o);
        d += __shfl_xor_sync(0xffffffffu, d, o);
    }
    if (lane == 0) {
        g_es1[warp] = __expf(s);
        g_es2[warp] = __expf(0.2f * s);
        g_ed1[warp] = __expf(d);
        g_ed2[warp] = __expf(0.2f * d);
    }
}

// ---------------- tensor-core attention, one-pass softmax --------------------
// P single fp16 (row-scaled, cancels); H single fp16: 2 MMAs per (ks,np).
#define PPITCH 72     /* halfs; 144B rows */
#define HPITCH 104    /* halfs; 208B rows -> conflict-free ldmatrix.trans */
#define AT_E1 0
#define AT_E2 2048
#define AT_L  4096
#define AT_MX 4352
#define AT_PH 4608
#define AT_HH (AT_PH + 64*PPITCH*2)
#define ATTN_SMEM (AT_HH + 64*HPITCH*2)

__global__ __launch_bounds__(256) void attn_mma_kernel(
    const float* __restrict__ adj, const float* __restrict__ bias)
{
    extern __shared__ char asm_buf[];
    float* shE1 = (float*)(asm_buf + AT_E1);
    float* shE2 = (float*)(asm_buf + AT_E2);
    float* shL  = (float*)(asm_buf + AT_L);
    float* shMx = (float*)(asm_buf + AT_MX);
    __half* sPh = (__half*)(asm_buf + AT_PH);
    uint32_t uHh = smem_u32(asm_buf + AT_HH);

    int bh = blockIdx.x;
    int b = bh >> 3, hd = bh & 7;
    int i0 = blockIdx.y << 6;
    int tid = threadIdx.x, lane = tid & 31, wid = tid >> 5;
    int wm = wid >> 1, wn = wid & 1;

    float mloc = 0.f;
    for (int e = tid; e < NN; e += 256) {
        float v1 = g_ed1[(size_t)bh * NN + e];
        shE1[e] = v1;
        mloc = fmaxf(mloc, v1);
        shE2[e] = g_ed2[(size_t)bh * NN + e];
    }
#pragma unroll
    for (int o = 16; o; o >>= 1)
        mloc = fmaxf(mloc, __shfl_xor_sync(0xffffffffu, mloc, o));
    if (lane == 0) shMx[wid] = mloc;
    __syncthreads();
    float maxE1 = shMx[0];
#pragma unroll
    for (int w = 1; w < 8; w++) maxE1 = fmaxf(maxE1, shMx[w]);

    int si = tid >> 2, jg = tid & 3;
    float f1 = g_es1[(size_t)bh * NN + i0 + si];
    float f2 = g_es2[(size_t)bh * NN + i0 + si];
    float q1m = f1 * maxE1;
    float rsc = q1m > 1.f ? 1.f / q1m : 1.f;    // row scale (cancels in p/l)
    const float* adjrow = adj + ((size_t)b * NN + i0 + si) * NN;
    float lpriv = 0.f;

    int rA = wm * 16 + (lane >> 2);        // acc rows rA, rA+8
    float acc[6][4];
#pragma unroll
    for (int nt = 0; nt < 6; nt++)
#pragma unroll
        for (int e = 0; e < 4; e++) acc[nt][e] = 0.f;

    const __half* hbh = g_hh + (size_t)bh * NN * FF;

    int kr_l = lane & 15;
    int nc_l = (lane >> 4) * 8;
    uint32_t aoff0 = (uint32_t)rA * (PPITCH * 2) + (uint32_t)(lane & 3) * 4;

    for (int jt = 0; jt < 8; jt++) {
        int j0 = jt << 6;
#pragma unroll
        for (int t = 0; t < 3; t++) {
            int cid = tid + t * 256;      // 0..767
            int row = cid / 12, c16 = cid % 12;
            uint32_t dst = (uint32_t)row * 208 + (uint32_t)c16 * 16;
            cpasync16(uHh + dst, hbh + (size_t)(j0 + row) * FF + c16 * 8);
        }
        CP_COMMIT();

        int jb = j0 + (jg << 4);
        const float4* arow4 = reinterpret_cast<const float4*>(adjrow + jb);
        float pv[16];
#pragma unroll
        for (int kk = 0; kk < 4; kk++) {
            float4 av = arow4[kk];
            float am[4] = {av.x, av.y, av.z, av.w};
#pragma unroll
            for (int e = 0; e < 4; e++) {
                int k = kk * 4 + e;
                float q1 = f1 * shE1[jb + k];
                float p = q1 > 1.f ? q1 : f2 * shE2[jb + k];
                p = am[e] > 0.f ? p * rsc : 0.f;
                pv[k] = p;
                lpriv += p;
            }
        }
        int pbase = si * PPITCH + (jg << 4);
#pragma unroll
        for (int k = 0; k < 16; k += 2) {
            __half2 h2;
            h2.x = __float2half_rn(pv[k]);
            h2.y = __float2half_rn(pv[k + 1]);
            *(__half2*)(sPh + pbase + k) = h2;
        }

        cp_wait<0>();
        __syncthreads();

#pragma unroll
        for (int ks = 0; ks < 4; ks++) {
            int k0 = ks * 16;
            uint32_t ah[4];
            {
                const char* ph = (const char*)sPh;
                uint32_t o = aoff0 + (uint32_t)k0 * 2;
                ah[0] = *(const uint32_t*)(ph + o);
                ah[1] = *(const uint32_t*)(ph + o + 8 * PPITCH * 2);
                ah[2] = *(const uint32_t*)(ph + o + 16);
                ah[3] = *(const uint32_t*)(ph + o + 8 * PPITCH * 2 + 16);
            }
#pragma unroll
            for (int np = 0; np < 3; np++) {
                int n0 = wn * 48 + np * 16;
                uint32_t boff = (uint32_t)(k0 + kr_l) * 208
                              + (uint32_t)(n0 + nc_l) * 2;
                uint32_t bH[4];
                ldsm4t(bH, uHh + boff);
                mma_f16(acc[np * 2],     ah, bH[0], bH[1]);
                mma_f16(acc[np * 2 + 1], ah, bH[2], bH[3]);
            }
        }
        __syncthreads();
    }

    lpriv += __shfl_xor_sync(0xffffffffu, lpriv, 1);
    lpriv += __shfl_xor_sync(0xffffffffu, lpriv, 2);
    if (jg == 0) shL[si] = lpriv;
    __syncthreads();

    float inv1 = 1.f / shL[rA];
    float inv2 = 1.f / shL[rA + 8];
    size_t ob = (((size_t)hd * BB + b) * NN + i0) * FF;
#pragma unroll
    for (int nt = 0; nt < 6; nt++) {
        int col = wn * 48 + nt * 8 + (lane & 3) * 2;
        float b0v = bias[col], b1v = bias[col + 1];
        float2 o1; o1.x = acc[nt][0] * inv1 + b0v; o1.y = acc[nt][1] * inv1 + b1v;
        *(float2*)(g_att + ob + (size_t)rA * FF + col) = o1;
        float2 o2; o2.x = acc[nt][2] * inv2 + b0v; o2.y = acc[nt][3] * inv2 + b1v;
        *(float2*)(g_att + ob + (size_t)(rA + 8) * FF + col) = o2;
    }
}

// ---------------- y = gate*elu(att) + (1-gate)*x (+ optional fp16 out) -------
__global__ void combine_split_kernel(const float* __restrict__ xin,
                                     float* __restrict__ yout,
                                     __half* __restrict__ hi)
{
    int i = blockIdx.x * blockDim.x + threadIdx.x;
    if (i >= BB * NN * DD) return;
    float a = g_att[i];
    float e = a > 0.f ? a : expm1f(a);
    float g = g_gate[i];
    float y = g * e + (1.f - g) * xin[i];
    yout[i] = y;
    hi[i] = __float2half_rn(y);
}

__global__ void combine_kernel(const float* __restrict__ xin, float* __restrict__ yout)
{
    int i = blockIdx.x * blockDim.x + threadIdx.x;
    if (i >= BB * NN * DD) return;
    float a = g_att[i];
    float e = a > 0.f ? a : expm1f(a);
    float g = g_gate[i];
    yout[i] = g * e + (1.f - g) * xin[i];
}

// -----------------------------------------------------------------------------
extern "C" void kernel_launch(void* const* d_in, const int* in_sizes, int n_in,
                              void* d_out, int out_size)
{
    const float* emb = (const float*)d_in[0];
    const float* adj = (const float*)d_in[1];
    const float* W0  = (const float*)d_in[3];
    const float* b0  = (const float*)d_in[4];
    const float* as0 = (const float*)d_in[5];
    const float* ad0 = (const float*)d_in[6];
    const float* Hw0 = (const float*)d_in[7];
    const float* Hb0 = (const float*)d_in[8];
    const float* W1  = (const float*)d_in[9];
    const float* b1  = (const float*)d_in[10];
    const float* as1 = (const float*)d_in[11];
    const float* ad1 = (const float*)d_in[12];
    const float* Hw1 = (const float*)d_in[13];
    const float* Hb1 = (const float*)d_in[14];
    float* out = (float*)d_out;

    cudaFuncSetAttribute(gemm_mma_kernel,
                         cudaFuncAttributeMaxDynamicSharedMemorySize, GEMM_SMEM);
    cudaFuncSetAttribute(attn_mma_kernel,
                         cudaFuncAttributeMaxDynamicSharedMemorySize, ATTN_SMEM);

    void* p;
    cudaGetSymbolAddress(&p, g_x1);   float* x1  = (float*)p;
    cudaGetSymbolAddress(&p, g_Ah);   __half* ah  = (__half*)p;
    cudaGetSymbolAddress(&p, g_Bh);   __half* bh  = (__half*)p;

    int prep_blocks = (GN * GK + 255) / 256;
    prep_kernel<<<prep_blocks, 256>>>(W0, Hw0, bh);
    prep_kernel<<<prep_blocks, 256>>>(W1, Hw1, bh + (size_t)GN * GK);

    int cvt_blocks = (GM * GK + 255) / 256;
    dim3 gemm_grid(GN / 128, GM / 256);
    int sd_blocks = (BB * HH * NN * 32 + 255) / 256;
    dim3 attn_grid(BB * HH, NN / 64);
    int cmb_blocks = (BB * NN * DD + 255) / 256;

    // layer 0
    cvt_kernel<<<cvt_blocks, 256>>>(emb, ah, GM * GK);
    gemm_mma_kernel<<<gemm_grid, 512, GEMM_SMEM>>>(ah, bh, Hb0);
    sd_kernel<<<sd_blocks, 256>>>(as0, ad0);
    attn_mma_kernel<<<attn_grid, 256, ATTN_SMEM>>>(adj, b0);
    combine_split_kernel<<<cmb_blocks, 256>>>(emb, x1, ah);

    // layer 1
    gemm_mma_kernel<<<gemm_grid, 512, GEMM_SMEM>>>(ah, bh + (size_t)GN * GK, Hb1);
    sd_kernel<<<sd_blocks, 256>>>(as1, ad1);
    attn_mma_kernel<<<attn_grid, 256, ATTN_SMEM>>>(adj, b1);
    combine_kernel<<<cmb_blocks, 256>>>(x1, out);
}

// round 17
// speedup vs baseline: 1.5230x; 1.1482x over previous
#include <cuda_runtime.h>
#include <cuda_fp16.h>
#include <math.h>
#include <stdint.h>

#define BB 16
#define NN 512
#define DD 768
#define HH 8
#define FF 96
#define GM (BB*NN)      /* 8192 rows */
#define GN (2*DD)       /* 1536 cols: [0,768)=h proj, [768,1536)=gate */
#define GK DD           /* 768 */

// ---------------- scratch (device globals; no allocs allowed) ----------------
__device__ __half g_hh[BB*HH*NN*FF];        // fp16 h, [bh][n][f]
__device__ float g_att[BB*HH*NN*FF];        // [h][b][n][f]
__device__ float g_es1[BB*HH*NN];           // exp(s)
__device__ float g_es2[BB*HH*NN];           // exp(0.2 s)
__device__ float g_ed1[BB*HH*NN];           // exp(d)
__device__ float g_ed2[BB*HH*NN];           // exp(0.2 d)
__device__ float g_gate[BB*NN*DD];          // sigmoid already applied (linear)
__device__ float g_x1[BB*NN*DD];            // layer-0 output
__device__ __half g_Ah[GM*GK];              // fp16 activations
__device__ __half g_Bh[2][GN*GK];           // packed weights fp16 [N=1536][K=768]
__device__ uint32_t g_adjbits[BB*NN*NN/32]; // adjacency bitmask (524 KB)

// ============================ PTX helpers (base sm_103 only) =================
__device__ __forceinline__ uint32_t smem_u32(const void* p) {
    uint32_t a;
    asm("{ .reg .u64 t; cvta.to.shared.u64 t, %1; cvt.u32.u64 %0, t; }"
        : "=r"(a) : "l"(p));
    return a;
}

__device__ __forceinline__ void cpasync16(uint32_t saddr, const void* g) {
    asm volatile("cp.async.cg.shared.global [%0], [%1], 16;"
                 :: "r"(saddr), "l"(g) : "memory");
}
#define CP_COMMIT() asm volatile("cp.async.commit_group;" ::: "memory")
template<int N> __device__ __forceinline__ void cp_wait() {
    asm volatile("cp.async.wait_group %0;" :: "n"(N) : "memory");
}

__device__ __forceinline__ void ldsm4(uint32_t* r, uint32_t addr) {
    asm volatile("ldmatrix.sync.aligned.m8n8.x4.shared.b16 {%0,%1,%2,%3}, [%4];"
                 : "=r"(r[0]), "=r"(r[1]), "=r"(r[2]), "=r"(r[3]) : "r"(addr));
}
__device__ __forceinline__ void ldsm4t(uint32_t* r, uint32_t addr) {
    asm volatile("ldmatrix.sync.aligned.m8n8.x4.trans.shared.b16 {%0,%1,%2,%3}, [%4];"
                 : "=r"(r[0]), "=r"(r[1]), "=r"(r[2]), "=r"(r[3]) : "r"(addr));
}

__device__ __forceinline__ void mma_f16(float* c, const uint32_t* a,
                                        uint32_t b0, uint32_t b1) {
    asm volatile(
        "mma.sync.aligned.m16n8k16.row.col.f32.f16.f16.f32 "
        "{%0,%1,%2,%3}, {%4,%5,%6,%7}, {%8,%9}, {%0,%1,%2,%3};"
        : "+f"(c[0]), "+f"(c[1]), "+f"(c[2]), "+f"(c[3])
        : "r"(a[0]), "r"(a[1]), "r"(a[2]), "r"(a[3]), "r"(b0), "r"(b1));
}

// swizzle for 128B rows (GEMM tiles)
#define SWZ128(o) ((uint32_t)(o) ^ ((((uint32_t)(o)) >> 3) & 0x70u))

// ---------------- adj -> bitmask (one pass) -----------------------------------
__global__ void adjbits_kernel(const float* __restrict__ adj, int n)
{
    int i = blockIdx.x * blockDim.x + threadIdx.x;
    if (i >= n) return;
    uint32_t m = __ballot_sync(0xffffffffu, adj[i] > 0.f);
    if ((threadIdx.x & 31) == 0) g_adjbits[i >> 5] = m;
}

// ---------------- fp32 -> fp16 activations (vectorized) -----------------------
__global__ void cvt_kernel(const float* __restrict__ x,
                           __half* __restrict__ hi, int n4)
{
    int i = blockIdx.x * blockDim.x + threadIdx.x;
    if (i >= n4) return;
    float4 v = ((const float4*)x)[i];
    __half2 a = __half2(__float2half_rn(v.x), __float2half_rn(v.y));
    __half2 b = __half2(__float2half_rn(v.z), __float2half_rn(v.w));
    ((__half2*)hi)[i * 2]     = a;
    ((__half2*)hi)[i * 2 + 1] = b;
}

// ---------------- pack W [H,D,F] and Hw^T into Bh [N=1536][K=768] fp16 -------
__global__ void prep_kernel(const float* __restrict__ W,
                            const float* __restrict__ Hw,
                            __half* __restrict__ bh)
{
    int idx = blockIdx.x * blockDim.x + threadIdx.x;
    if (idx >= GN * GK) return;
    int c = idx / GK;
    int k = idx - c * GK;
    float v;
    if (c < DD) {
        int hd = c / FF, f = c - hd * FF;
        v = W[((size_t)hd * GK + k) * FF + f];
    } else {
        v = Hw[(size_t)(c - DD) * GK + k];      // Hw^T
    }
    bh[idx] = __float2half_rn(v);
}

// ---------------- mma.sync GEMM: D[8192][1536] = A[8192][768] @ B^T ----------
#define KCH 64
#define A_STAGE 32768          /* 256 rows x 128B */
#define B_STAGE 16384          /* 128 rows x 128B */
#define STAGE_BYTES (A_STAGE + B_STAGE)
#define GEMM_SMEM (3*STAGE_BYTES)

__global__ __launch_bounds__(512, 1) void gemm_mma_kernel(
    const __half* __restrict__ Ah,
    const __half* __restrict__ Bh, const float* __restrict__ Hb)
{
    extern __shared__ char smem[];
    uint32_t sb = smem_u32(smem);

    int tid = threadIdx.x;
    int lane = tid & 31, wid = tid >> 5;
    int wm = wid >> 2, wn = wid & 3;           // 4(M) x 4(N) warps
    int bx = blockIdx.x, by = blockIdx.y;

    const __half* pa = Ah + (size_t)(by * 256) * GK;
    const __half* pb = Bh + (size_t)(bx * 128) * GK;

    int ra = tid >> 1, ha = tid & 1;
    int rb = tid >> 2, qb = tid & 3;
    uint32_t soA[4], soB[2];
#pragma unroll
    for (int i = 0; i < 4; i++)
        soA[i] = SWZ128((uint32_t)ra * 128 + (uint32_t)ha * 64 + (uint32_t)i * 16);
#pragma unroll
    for (int i = 0; i < 2; i++)
        soB[i] = SWZ128((uint32_t)rb * 128 + (uint32_t)qb * 32 + (uint32_t)i * 16);

    int sub = lane >> 3, sr = lane & 7;
    uint32_t offA0[4], offB0[2];
#pragma unroll
    for (int mt = 0; mt < 4; mt++)
        offA0[mt] = SWZ128((wm * 64 + mt * 16 + (sub & 1) * 8 + sr) * 128
                           + (sub >> 1) * 16);
#pragma unroll
    for (int nb = 0; nb < 2; nb++)
        offB0[nb] = SWZ128((wn * 32 + nb * 16 + (sub >> 1) * 8 + sr) * 128
                           + (sub & 1) * 16);

    float acc[4][4][4];
#pragma unroll
    for (int mt = 0; mt < 4; mt++)
#pragma unroll
        for (int j = 0; j < 4; j++)
#pragma unroll
            for (int e = 0; e < 4; e++) acc[mt][j][e] = 0.f;

#define GEMM_PF(st, kc) do {                                         \
        size_t offa = (size_t)ra * GK + (kc) + ha * 32;              \
        _Pragma("unroll")                                            \
        for (int i = 0; i < 4; i++)                                  \
            cpasync16((st) + soA[i], pa + offa + i * 8);             \
        size_t offb = (size_t)rb * GK + (kc) + qb * 16;              \
        _Pragma("unroll")                                            \
        for (int i = 0; i < 2; i++)                                  \
            cpasync16((st) + A_STAGE + soB[i], pb + offb + i * 8);   \
    } while (0)

    GEMM_PF(sb, 0);
    CP_COMMIT();
    GEMM_PF(sb + STAGE_BYTES, KCH);
    CP_COMMIT();

    const int NCHUNK = GK / KCH;     // 12
#pragma unroll 1
    for (int c = 0; c < NCHUNK; c++) {
        if (c + 1 < NCHUNK) { cp_wait<1>(); } else { cp_wait<0>(); }
        __syncthreads();
        if (c + 2 < NCHUNK) {
            GEMM_PF(sb + (uint32_t)((c + 2) % 3) * STAGE_BYTES, (c + 2) * KCH);
            CP_COMMIT();
        }

        uint32_t bs = sb + (uint32_t)(c % 3) * STAGE_BYTES;
#pragma unroll
        for (int ks = 0; ks < 4; ks++) {
            uint32_t kx = (uint32_t)ks << 5;   // SW128: col bits 5-6 XOR
            uint32_t aF[4][4], bF[2][4];
#pragma unroll
            for (int mt = 0; mt < 4; mt++)
                ldsm4(aF[mt], bs + (offA0[mt] ^ kx));
#pragma unroll
            for (int nb = 0; nb < 2; nb++)
                ldsm4(bF[nb], bs + A_STAGE + (offB0[nb] ^ kx));
#pragma unroll
            for (int mt = 0; mt < 4; mt++) {
#pragma unroll
                for (int j = 0; j < 4; j++) {
                    int nb = j >> 1, hf = (j & 1) * 2;
                    mma_f16(acc[mt][j], aF[mt], bF[nb][hf], bF[nb][hf + 1]);
                }
            }
        }
    }

    // ------------- epilogue: fp16 h (half2) / sigmoid gate (float2) -----------
    int g = lane >> 2, tig = lane & 3;
    int row_base = by * 256 + wm * 64;
    int col_base = bx * 128 + wn * 32;
    if (bx < 6) {
#pragma unroll
        for (int mt = 0; mt < 4; mt++) {
#pragma unroll
            for (int j = 0; j < 4; j++) {
                int col = col_base + j * 8 + tig * 2;   // even; pair never straddles hd
                int hd = col / FF, f = col - hd * FF;
                int rA = row_base + mt * 16 + g;
                int b0i = rA >> 9, n0i = rA & 511;
                size_t i0x = (((size_t)(b0i * HH + hd)) * NN + n0i) * FF + f;
                *(__half2*)(g_hh + i0x) = __half2(
                    __float2half_rn(acc[mt][j][0]), __float2half_rn(acc[mt][j][1]));
                int rB = rA + 8;
                int b1i = rB >> 9, n1i = rB & 511;
                size_t i1x = (((size_t)(b1i * HH + hd)) * NN + n1i) * FF + f;
                *(__half2*)(g_hh + i1x) = __half2(
                    __float2half_rn(acc[mt][j][2]), __float2half_rn(acc[mt][j][3]));
            }
        }
    } else {
        // gate stored SEMANTIC-LINEAR: g_gate[(b*N+n)*D + o]
#pragma unroll
        for (int mt = 0; mt < 4; mt++) {
#pragma unroll
            for (int j = 0; j < 4; j++) {
                int col = col_base + j * 8 + tig * 2;
                int o = col - DD;
                float hb0 = Hb[o], hb1 = Hb[o + 1];
                int rA = row_base + mt * 16 + g;
                float2 p0;
                p0.x = 1.f / (1.f + __expf(-(acc[mt][j][0] + hb0)));
                p0.y = 1.f / (1.f + __expf(-(acc[mt][j][1] + hb1)));
                *(float2*)(g_gate + (size_t)rA * DD + o) = p0;
                float2 p1;
                p1.x = 1.f / (1.f + __expf(-(acc[mt][j][2] + hb0)));
                p1.y = 1.f / (1.f + __expf(-(acc[mt][j][3] + hb1)));
                *(float2*)(g_gate + (size_t)(rA + 8) * DD + o) = p1;
            }
        }
    }
#undef GEMM_PF
}

// ---------------- s/d reductions + exp factors: one warp per (b,h,n) row -----
__global__ void sd_kernel(const float* __restrict__ asrc, const float* __restrict__ adst)
{
    int gtid = blockIdx.x * blockDim.x + threadIdx.x;
    int warp = gtid >> 5;
    int lane = gtid & 31;
    if (warp >= BB * HH * NN) return;
    int hd = (warp >> 9) & 7;
    const __half* rh = g_hh + (size_t)warp * FF;
    float s = 0.f, d = 0.f;
#pragma unroll
    for (int k = 0; k < 3; k++) {
        int f = lane + k * 32;
        float t = tanhf(__half2float(rh[f]));
        s += t * asrc[hd * FF + f];
        d += t * adst[hd * FF + f];
    }
#pragma unroll
    for (int o = 16; o; o >>= 1) {
        s += __shfl_xor_sync(0xffffffffu, s, o);
        d += __shfl_xor_sync(0xffffffffu, d, o);
    }
    if (lane == 0) {
        g_es1[warp] = __expf(s);
        g_es2[warp] = __expf(0.2f * s);
        g_ed1[warp] = __expf(d);
        g_ed2[warp] = __expf(0.2f * d);
    }
}

// ---------------- tensor-core attention, one-pass softmax --------------------
// adjacency via bitmask words (L1-resident); P single fp16 row-scaled; H fp16.
#define PPITCH 72     /* halfs; 144B rows */
#define HPITCH 104    /* halfs; 208B rows -> conflict-free ldmatrix.trans */
#define AT_E1 0
#define AT_E2 2048
#define AT_L  4096
#define AT_MX 4352
#define AT_PH 4608
#define AT_HH (AT_PH + 64*PPITCH*2)
#define ATTN_SMEM (AT_HH + 64*HPITCH*2)

__global__ __launch_bounds__(256) void attn_mma_kernel(
    const float* __restrict__ bias)
{
    extern __shared__ char asm_buf[];
    float* shE1 = (float*)(asm_buf + AT_E1);
    float* shE2 = (float*)(asm_buf + AT_E2);
    float* shL  = (float*)(asm_buf + AT_L);
    float* shMx = (float*)(asm_buf + AT_MX);
    __half* sPh = (__half*)(asm_buf + AT_PH);
    uint32_t uHh = smem_u32(asm_buf + AT_HH);

    int bh = blockIdx.x;
    int b = bh >> 3, hd = bh & 7;
    int i0 = blockIdx.y << 6;
    int tid = threadIdx.x, lane = tid & 31, wid = tid >> 5;
    int wm = wid >> 1, wn = wid & 1;

    float mloc = 0.f;
    for (int e = tid; e < NN; e += 256) {
        float v1 = g_ed1[(size_t)bh * NN + e];
        shE1[e] = v1;
        mloc = fmaxf(mloc, v1);
        shE2[e] = g_ed2[(size_t)bh * NN + e];
    }
#pragma unroll
    for (int o = 16; o; o >>= 1)
        mloc = fmaxf(mloc, __shfl_xor_sync(0xffffffffu, mloc, o));
    if (lane == 0) shMx[wid] = mloc;
    __syncthreads();
    float maxE1 = shMx[0];
#pragma unroll
    for (int w = 1; w < 8; w++) maxE1 = fmaxf(maxE1, shMx[w]);

    int si = tid >> 2, jg = tid & 3;
    float f1 = g_es1[(size_t)bh * NN + i0 + si];
    float f2 = g_es2[(size_t)bh * NN + i0 + si];
    float q1m = f1 * maxE1;
    float rsc = q1m > 1.f ? 1.f / q1m : 1.f;    // row scale (cancels in p/l)
    const uint32_t* adjw = g_adjbits + ((size_t)b * NN + i0 + si) * (NN / 32);
    float lpriv = 0.f;

    int rA = wm * 16 + (lane >> 2);        // acc rows rA, rA+8
    float acc[6][4];
#pragma unroll
    for (int nt = 0; nt < 6; nt++)
#pragma unroll
        for (int e = 0; e < 4; e++) acc[nt][e] = 0.f;

    const __half* hbh = g_hh + (size_t)bh * NN * FF;

    int kr_l = lane & 15;
    int nc_l = (lane >> 4) * 8;
    uint32_t aoff0 = (uint32_t)rA * (PPITCH * 2) + (uint32_t)(lane & 3) * 4;

    for (int jt = 0; jt < 8; jt++) {
        int j0 = jt << 6;
#pragma unroll
        for (int t = 0; t < 3; t++) {
            int cid = tid + t * 256;      // 0..767
            int row = cid / 12, c16 = cid % 12;
            uint32_t dst = (uint32_t)row * 208 + (uint32_t)c16 * 16;
            cpasync16(uHh + dst, hbh + (size_t)(j0 + row) * FF + c16 * 8);
        }
        CP_COMMIT();

        int jb = j0 + (jg << 4);
        uint32_t wbits = adjw[(jt << 1) + (jg >> 1)] >> ((jg & 1) * 16);
        float pv[16];
#pragma unroll
        for (int k = 0; k < 16; k++) {
            float q1 = f1 * shE1[jb + k];
            float p = q1 > 1.f ? q1 : f2 * shE2[jb + k];
            p = (wbits >> k) & 1u ? p * rsc : 0.f;
            pv[k] = p;
            lpriv += p;
        }
        int pbase = si * PPITCH + (jg << 4);
#pragma unroll
        for (int k = 0; k < 16; k += 2) {
            __half2 h2;
            h2.x = __float2half_rn(pv[k]);
            h2.y = __float2half_rn(pv[k + 1]);
            *(__half2*)(sPh + pbase + k) = h2;
        }

        cp_wait<0>();
        __syncthreads();

#pragma unroll
        for (int ks = 0; ks < 4; ks++) {
            int k0 = ks * 16;
            uint32_t ah[4];
            {
                const char* ph = (const char*)sPh;
                uint32_t o = aoff0 + (uint32_t)k0 * 2;
                ah[0] = *(const uint32_t*)(ph + o);
                ah[1] = *(const uint32_t*)(ph + o + 8 * PPITCH * 2);
                ah[2] = *(const uint32_t*)(ph + o + 16);
                ah[3] = *(const uint32_t*)(ph + o + 8 * PPITCH * 2 + 16);
            }
#pragma unroll
            for (int np = 0; np < 3; np++) {
                int n0 = wn * 48 + np * 16;
                uint32_t boff = (uint32_t)(k0 + kr_l) * 208
                              + (uint32_t)(n0 + nc_l) * 2;
                uint32_t bH[4];
                ldsm4t(bH, uHh + boff);
                mma_f16(acc[np * 2],     ah, bH[0], bH[1]);
                mma_f16(acc[np * 2 + 1], ah, bH[2], bH[3]);
            }
        }
        __syncthreads();
    }

    lpriv += __shfl_xor_sync(0xffffffffu, lpriv, 1);
    lpriv += __shfl_xor_sync(0xffffffffu, lpriv, 2);
    if (jg == 0) shL[si] = lpriv;
    __syncthreads();

    float inv1 = 1.f / shL[rA];
    float inv2 = 1.f / shL[rA + 8];
    size_t ob = (((size_t)hd * BB + b) * NN + i0) * FF;
#pragma unroll
    for (int nt = 0; nt < 6; nt++) {
        int col = wn * 48 + nt * 8 + (lane & 3) * 2;
        float b0v = bias[col], b1v = bias[col + 1];
        float2 o1; o1.x = acc[nt][0] * inv1 + b0v; o1.y = acc[nt][1] * inv1 + b1v;
        *(float2*)(g_att + ob + (size_t)rA * FF + col) = o1;
        float2 o2; o2.x = acc[nt][2] * inv2 + b0v; o2.y = acc[nt][3] * inv2 + b1v;
        *(float2*)(g_att + ob + (size_t)(rA + 8) * FF + col) = o2;
    }
}

// ---------------- y = gate*elu(att) + (1-gate)*x (vectorized) ----------------
__global__ void combine_split_kernel(const float* __restrict__ xin,
                                     float* __restrict__ yout,
                                     __half* __restrict__ hi)
{
    int i = blockIdx.x * blockDim.x + threadIdx.x;
    if (i >= BB * NN * DD / 4) return;
    float4 a = ((const float4*)g_att)[i];
    float4 g = ((const float4*)g_gate)[i];
    float4 x = ((const float4*)xin)[i];
    float4 y;
    y.x = g.x * (a.x > 0.f ? a.x : expm1f(a.x)) + (1.f - g.x) * x.x;
    y.y = g.y * (a.y > 0.f ? a.y : expm1f(a.y)) + (1.f - g.y) * x.y;
    y.z = g.z * (a.z > 0.f ? a.z : expm1f(a.z)) + (1.f - g.z) * x.z;
    y.w = g.w * (a.w > 0.f ? a.w : expm1f(a.w)) + (1.f - g.w) * x.w;
    ((float4*)yout)[i] = y;
    ((__half2*)hi)[i * 2]     = __half2(__float2half_rn(y.x), __float2half_rn(y.y));
    ((__half2*)hi)[i * 2 + 1] = __half2(__float2half_rn(y.z), __float2half_rn(y.w));
}

__global__ void combine_kernel(const float* __restrict__ xin, float* __restrict__ yout)
{
    int i = blockIdx.x * blockDim.x + threadIdx.x;
    if (i >= BB * NN * DD / 4) return;
    float4 a = ((const float4*)g_att)[i];
    float4 g = ((const float4*)g_gate)[i];
    float4 x = ((const float4*)xin)[i];
    float4 y;
    y.x = g.x * (a.x > 0.f ? a.x : expm1f(a.x)) + (1.f - g.x) * x.x;
    y.y = g.y * (a.y > 0.f ? a.y : expm1f(a.y)) + (1.f - g.y) * x.y;
    y.z = g.z * (a.z > 0.f ? a.z : expm1f(a.z)) + (1.f - g.z) * x.z;
    y.w = g.w * (a.w > 0.f ? a.w : expm1f(a.w)) + (1.f - g.w) * x.w;
    ((float4*)yout)[i] = y;
}

// -----------------------------------------------------------------------------
extern "C" void kernel_launch(void* const* d_in, const int* in_sizes, int n_in,
                              void* d_out, int out_size)
{
    const float* emb = (const float*)d_in[0];
    const float* adj = (const float*)d_in[1];
    const float* W0  = (const float*)d_in[3];
    const float* b0  = (const float*)d_in[4];
    const float* as0 = (const float*)d_in[5];
    const float* ad0 = (const float*)d_in[6];
    const float* Hw0 = (const float*)d_in[7];
    const float* Hb0 = (const float*)d_in[8];
    const float* W1  = (const float*)d_in[9];
    const float* b1  = (const float*)d_in[10];
    const float* as1 = (const float*)d_in[11];
    const float* ad1 = (const float*)d_in[12];
    const float* Hw1 = (const float*)d_in[13];
    const float* Hb1 = (const float*)d_in[14];
    float* out = (float*)d_out;

    cudaFuncSetAttribute(gemm_mma_kernel,
                         cudaFuncAttributeMaxDynamicSharedMemorySize, GEMM_SMEM);
    cudaFuncSetAttribute(attn_mma_kernel,
                         cudaFuncAttributeMaxDynamicSharedMemorySize, ATTN_SMEM);

    void* p;
    cudaGetSymbolAddress(&p, g_x1);   float* x1  = (float*)p;
    cudaGetSymbolAddress(&p, g_Ah);   __half* ah  = (__half*)p;
    cudaGetSymbolAddress(&p, g_Bh);   __half* bh  = (__half*)p;

    int prep_blocks = (GN * GK + 255) / 256;
    prep_kernel<<<prep_blocks, 256>>>(W0, Hw0, bh);
    prep_kernel<<<prep_blocks, 256>>>(W1, Hw1, bh + (size_t)GN * GK);
    int adjn = BB * NN * NN;
    adjbits_kernel<<<(adjn + 255) / 256, 256>>>(adj, adjn);

    int cvt_blocks = (GM * GK / 4 + 255) / 256;
    dim3 gemm_grid(GN / 128, GM / 256);
    int sd_blocks = (BB * HH * NN * 32 + 255) / 256;
    dim3 attn_grid(BB * HH, NN / 64);
    int cmb_blocks = (BB * NN * DD / 4 + 255) / 256;

    // layer 0
    cvt_kernel<<<cvt_blocks, 256>>>(emb, ah, GM * GK / 4);
    gemm_mma_kernel<<<gemm_grid, 512, GEMM_SMEM>>>(ah, bh, Hb0);
    sd_kernel<<<sd_blocks, 256>>>(as0, ad0);
    attn_mma_kernel<<<attn_grid, 256, ATTN_SMEM>>>(b0);
    combine_split_kernel<<<cmb_blocks, 256>>>(emb, x1, ah);

    // layer 1
    gemm_mma_kernel<<<gemm_grid, 512, GEMM_SMEM>>>(ah, bh + (size_t)GN * GK, Hb1);
    sd_kernel<<<sd_blocks, 256>>>(as1, ad1);
    attn_mma_kernel<<<attn_grid, 256, ATTN_SMEM>>>(b1);
    combine_kernel<<<cmb_blocks, 256>>>(x1, out);
}